// round 17
// baseline (speedup 1.0000x reference)
#include <cuda_runtime.h>
#include <cuda_fp16.h>
#include <cstdint>

// ---------------------------------------------------------------------------
#define M_ 16384           // B*S token rows
#define P_ 512             // prototypes (= N)
#define D_ 768             // feature dim (= K)
#define BM 64
#define BN 64
#define BKH 64             // K halves per stage (128 B per row)
#define NS (D_ / BKH)      // 12 stages
#define NTH 64             // 2 warps
#define ATILEB 8192        // 64 rows x 128 B
#define BTILEB 8192
#define STAGEB (ATILEB + BTILEB)
#define SMEM_BYTES (2 * STAGEB + 128)

__device__ __half g_a16[(size_t)M_ * D_];
__device__ __half g_b16[(size_t)P_ * D_];
__device__ float  g_xsq[M_];
__device__ float  g_psq[P_];

// ---------------------------------------------------------------------------
// Prep: one pass -> fp16 copies + exact f32 row norms + prototype passthrough.
// ---------------------------------------------------------------------------
__global__ void prep_kernel(const float* __restrict__ X,
                            const float* __restrict__ Pp,
                            float* __restrict__ proto_out) {
    const int r   = threadIdx.x >> 4;
    const int kq  = threadIdx.x & 15;
    const int row = blockIdx.x * 16 + r;
    const float* src;
    __half* dst16;
    float* dstn;
    float* passthru = nullptr;
    if (row < M_) {
        src = X + (size_t)row * D_;  dst16 = g_a16 + (size_t)row * D_;  dstn = g_xsq + row;
    } else {
        const int pr = row - M_;
        src = Pp + (size_t)pr * D_;  dst16 = g_b16 + (size_t)pr * D_;   dstn = g_psq + pr;
        passthru = proto_out + (size_t)pr * D_;
    }
    float s = 0.f;
    #pragma unroll
    for (int i = 0; i < 12; i++) {
        float4 v = *reinterpret_cast<const float4*>(src + i * 64 + kq * 4);
        s = fmaf(v.x, v.x, fmaf(v.y, v.y, fmaf(v.z, v.z, fmaf(v.w, v.w, s))));
        __half2 h01 = __floats2half2_rn(v.x, v.y);
        __half2 h23 = __floats2half2_rn(v.z, v.w);
        *reinterpret_cast<uint2*>(dst16 + i * 64 + kq * 4) =
            make_uint2(*reinterpret_cast<uint32_t*>(&h01),
                       *reinterpret_cast<uint32_t*>(&h23));
        if (passthru) *reinterpret_cast<float4*>(passthru + i * 64 + kq * 4) = v;
    }
    #pragma unroll
    for (int o = 8; o; o >>= 1) s += __shfl_xor_sync(0xffffffffu, s, o);
    if (kq == 0) *dstn = s;
}

// ---------------------------------------------------------------------------
__device__ __forceinline__ void cp_async16(uint32_t d, const void* s) {
    asm volatile("cp.async.cg.shared.global [%0], [%1], 16;" ::"r"(d), "l"(s));
}
#define CP_COMMIT() asm volatile("cp.async.commit_group;" ::: "memory")
#define CP_WAIT_1() asm volatile("cp.async.wait_group 1;" ::: "memory")
#define CP_WAIT_0() asm volatile("cp.async.wait_group 0;" ::: "memory")

#define LDSM_X4(r0, r1, r2, r3, a)                                             \
    asm volatile("ldmatrix.sync.aligned.m8n8.x4.shared.b16 {%0,%1,%2,%3}, [%4];" \
                 : "=r"(r0), "=r"(r1), "=r"(r2), "=r"(r3) : "r"(a))

#define MMA_F16A(c0, c1, a0, a1, a2, a3, b0, b1)                               \
    asm volatile("mma.sync.aligned.m16n8k16.row.col.f16.f16.f16.f16 "          \
                 "{%0,%1}, {%2,%3,%4,%5}, {%6,%7}, {%0,%1};"                   \
                 : "+r"(c0), "+r"(c1)                                          \
                 : "r"(a0), "r"(a1), "r"(a2), "r"(a3), "r"(b0), "r"(b1))

// ---------------------------------------------------------------------------
// Fused distance GEMM, fp16 tensor cores, fp16 accumulate.
// CTA tile 64x64, 2 warps (warp tile 64x32). 2-stage pipeline, 32 KB smem
// -> 7 CTAs/SM (14 warps/SM in 7 independent barrier domains).
//   C[m][n] = xsq[m] + psq[n] - 2 * sum_k A16[m][k] * B16[n][k]
// Smem per tile: row r (128 B), 16B unit u stored at (u ^ (r & 7)).
// ---------------------------------------------------------------------------
__global__ __launch_bounds__(NTH, 7)
void dist_f16acc7_kernel(float* __restrict__ C) {
    extern __shared__ __align__(16) char smem[];
    uint32_t sb0;
    asm("{ .reg .u64 t; cvta.to.shared.u64 t, %1; cvt.u32.u64 %0, t; }"
        : "=r"(sb0) : "l"(smem));
    const uint32_t sb = (sb0 + 127u) & ~127u;

    const int tid  = threadIdx.x;
    const int lane = tid & 31;
    const int warp = tid >> 5;       // 0..1 -> N half
    const int wn   = warp;
    const int bx   = blockIdx.x;     // N tile (0..7)
    const int by   = blockIdx.y;     // M tile (0..255)

    const __half* Ablk = g_a16 + (size_t)by * BM * D_;
    const __half* Bblk = g_b16 + (size_t)bx * BN * D_;

    // loader: A 512 + B 512 16B-units per stage -> 8 + 8 per thread
    const int lrow = tid >> 3;       // 0..7 (j adds 8)
    const int lu   = tid & 7;
    const uint32_t lsw = (uint32_t)((lu ^ (lrow & 7)) << 4);

    auto load_stage = [&](int s) {
        const uint32_t ab = sb + (uint32_t)(s & 1) * STAGEB;
        const uint32_t bb = ab + ATILEB;
        const int kf = s * BKH + lu * 8;
        #pragma unroll
        for (int j = 0; j < 8; j++) {
            const int row = lrow + j * 8;
            cp_async16(ab + (uint32_t)row * 128 + lsw,
                       Ablk + (size_t)row * D_ + kf);
            cp_async16(bb + (uint32_t)row * 128 + lsw,
                       Bblk + (size_t)row * D_ + kf);
        }
    };

    // ldmatrix per-lane components
    const int rA = (lane & 7) + ((lane >> 3) & 1) * 8;            // + i*16
    const int uA = lane >> 4;
    const int rB = wn * 32 + (lane & 7) + (lane >> 4) * 8;        // + jp*16
    const int uB = (lane >> 3) & 1;
    const uint32_t swz = (uint32_t)(lane & 7);

    uint32_t c[4][4][2];             // fp16x2 accumulators (64x32 warp tile)
    #pragma unroll
    for (int i = 0; i < 4; i++)
        #pragma unroll
        for (int j = 0; j < 4; j++) { c[i][j][0] = 0u; c[i][j][1] = 0u; }

    uint32_t a[2][4][4], b[2][2][4];

    auto frag_load = [&](int fb, uint32_t ab, uint32_t bb, int kk) {
        #pragma unroll
        for (int i = 0; i < 4; i++) {
            const uint32_t addr = ab + (uint32_t)(rA + i * 16) * 128
                + ((((uint32_t)(kk * 2 + uA)) ^ swz) << 4);
            LDSM_X4(a[fb][i][0], a[fb][i][1], a[fb][i][2], a[fb][i][3], addr);
        }
        #pragma unroll
        for (int jp = 0; jp < 2; jp++) {
            const uint32_t addr = bb + (uint32_t)(rB + jp * 16) * 128
                + ((((uint32_t)(kk * 2 + uB)) ^ swz) << 4);
            LDSM_X4(b[fb][jp][0], b[fb][jp][1], b[fb][jp][2], b[fb][jp][3], addr);
        }
    };

    load_stage(0); CP_COMMIT();

    for (int s = 0; s < NS; ++s) {
        if (s + 1 < NS) { load_stage(s + 1); CP_COMMIT(); CP_WAIT_1(); }
        else            { CP_WAIT_0(); }
        __syncthreads();                        // stage s visible

        const uint32_t ab = sb + (uint32_t)(s & 1) * STAGEB;
        const uint32_t bb = ab + ATILEB;

        frag_load(0, ab, bb, 0);
        #pragma unroll
        for (int kk = 0; kk < 4; kk++) {        // 4 x k16 per stage
            const int fb = kk & 1;
            if (kk + 1 < 4) frag_load(fb ^ 1, ab, bb, kk + 1);
            #pragma unroll
            for (int i = 0; i < 4; i++) {
                #pragma unroll
                for (int jp = 0; jp < 2; jp++) {
                    MMA_F16A(c[i][jp * 2][0], c[i][jp * 2][1],
                             a[fb][i][0], a[fb][i][1], a[fb][i][2], a[fb][i][3],
                             b[fb][jp][0], b[fb][jp][1]);
                    MMA_F16A(c[i][jp * 2 + 1][0], c[i][jp * 2 + 1][1],
                             a[fb][i][0], a[fb][i][1], a[fb][i][2], a[fb][i][3],
                             b[fb][jp][2], b[fb][jp][3]);
                }
            }
        }
        __syncthreads();                        // buf (s&1) free for stage s+2
    }

    // ---- epilogue: dist = xsq + psq - 2*cross ----
    const int g = lane >> 2;
    const int t = lane & 3;
    #pragma unroll
    for (int i = 0; i < 4; i++) {
        const int mg0 = by * BM + i * 16 + g;
        const float x0 = g_xsq[mg0];
        const float x1 = g_xsq[mg0 + 8];
        float* row0 = C + (size_t)mg0 * P_;
        float* row1 = C + (size_t)(mg0 + 8) * P_;
        #pragma unroll
        for (int j = 0; j < 4; j++) {
            const int ng = bx * BN + wn * 32 + j * 8 + 2 * t;
            const float p0 = g_psq[ng];
            const float p1 = g_psq[ng + 1];
            const float2 f0 = __half22float2(*reinterpret_cast<__half2*>(&c[i][j][0]));
            const float2 f1 = __half22float2(*reinterpret_cast<__half2*>(&c[i][j][1]));
            float2 v0, v1;
            v0.x = x0 + p0 - 2.f * f0.x;
            v0.y = x0 + p1 - 2.f * f0.y;
            v1.x = x1 + p0 - 2.f * f1.x;
            v1.y = x1 + p1 - 2.f * f1.y;
            *reinterpret_cast<float2*>(row0 + ng) = v0;
            *reinterpret_cast<float2*>(row1 + ng) = v1;
        }
    }
}

// ---------------------------------------------------------------------------
extern "C" void kernel_launch(void* const* d_in, const int* in_sizes, int n_in,
                              void* d_out, int out_size) {
    const float* inputs = (const float*)d_in[0];   // [M_, D_]
    const float* protos = (const float*)d_in[1];   // [P_, D_]
    float* out = (float*)d_out;

    // 1) fp16 copies + exact f32 norms + prototype passthrough (single pass)
    prep_kernel<<<(M_ + P_) / 16, 256>>>(inputs, protos, out + (size_t)M_ * P_);

    // 2) fused distance GEMM (fp16 accumulate, 7 CTAs/SM)
    cudaFuncSetAttribute(dist_f16acc7_kernel,
                         cudaFuncAttributeMaxDynamicSharedMemorySize, SMEM_BYTES);
    dim3 grid(P_ / BN, M_ / BM);   // (8, 256)
    dist_f16acc7_kernel<<<grid, NTH, SMEM_BYTES>>>(out);
}